// round 8
// baseline (speedup 1.0000x reference)
#include <cuda_runtime.h>
#include <cuda_bf16.h>
#include <cuda_fp16.h>
#include <cstdint>

// Problem constants
#define BB    2
#define LL    2048
#define DIM   1024
#define DM    512
#define DI    1024
#define E2    2048      // 2*DI
#define MROWS 4096      // BB*LL
#define DS    16        // D_STATE
#define DTR   32        // DT_RANK
#define NC    16        // scan chunks
#define LC    128       // chunk length (NC*LC == LL)
#define KSPLIT 4        // split-K factor for xproj GEMM
#define M64   (MROWS * 64)

// ---------------- scratch (static device memory; no allocation allowed) ----------
__device__ float g_xc   [2][MROWS * DI];         // conv+silu output (fp32 for scan)
__device__ float g_part [2][KSPLIT][M64];        // split-K partials for xproj (dt|B|C)
__device__ float g_delta[2][MROWS * DI];         // softplus(dt @ dt_w^T + dt_b)
__device__ float g_cs   [2][BB * NC * DI];       // per-chunk sum of delta
__device__ float g_he   [2][BB * NC * DI * DS];  // chunk-local h_end
__device__ float g_hs   [2][BB * NC * DI * DS];  // chunk h_start (after fixup)

// fp16 operands (all GEMMs single-fp16)
__device__ __half g_xf  [MROWS * DIM];           // x
__device__ __half g_w1f [2][E2 * DM];            // in_w
__device__ __half g_wxf [2][64 * DI];            // xproj_w
__device__ __half g_wof [2][DM * DI];            // out_w
__device__ __half g_xzf [2][MROWS * E2];         // in-proj output (xh | z), fp16
__device__ __half g_xcf [2][MROWS * DI];         // conv output fp16 (xproj A operand)
__device__ __half g_ymf [2][MROWS * DI];         // scan output fp16 (GEMM3 A operand)

// ---------------- helpers ----------------------------------------------------------
__device__ __forceinline__ void mma_f16(float* c, const uint32_t* a, const uint32_t* b) {
    asm volatile(
        "mma.sync.aligned.m16n8k16.row.col.f32.f16.f16.f32 "
        "{%0,%1,%2,%3}, {%4,%5,%6,%7}, {%8,%9}, {%0,%1,%2,%3};\n"
        : "+f"(c[0]), "+f"(c[1]), "+f"(c[2]), "+f"(c[3])
        : "r"(a[0]), "r"(a[1]), "r"(a[2]), "r"(a[3]), "r"(b[0]), "r"(b[1]));
}

__device__ __forceinline__ void ldsm_x4(uint32_t& r0, uint32_t& r1, uint32_t& r2, uint32_t& r3, uint32_t a) {
    asm volatile("ldmatrix.sync.aligned.m8n8.x4.shared.b16 {%0,%1,%2,%3}, [%4];"
                 : "=r"(r0), "=r"(r1), "=r"(r2), "=r"(r3) : "r"(a));
}

#define CPASYNC16(dst, src) asm volatile("cp.async.cg.shared.global [%0], [%1], 16;\n" :: "r"(dst), "l"(src))
#define CPCOMMIT()          asm volatile("cp.async.commit_group;\n")
#define CPWAIT1()           asm volatile("cp.async.wait_group 1;\n")

__device__ __forceinline__ uint32_t smem_u32(const void* p) {
    return (uint32_t)__cvta_generic_to_shared(p);
}

__device__ __forceinline__ void half_body(const float* __restrict__ in,
                                          __half* __restrict__ o, int i)
{
    float4 v = reinterpret_cast<const float4*>(in)[i];
    __half2* op = reinterpret_cast<__half2*>(o) + 2 * i;
    op[0] = __floats2half2_rn(v.x, v.y);
    op[1] = __floats2half2_rn(v.z, v.w);
}

// ---------------- prep: residual copy + x fp16 + all weight fp16, ONE launch -------
__global__ void prep_all_kernel(const float* __restrict__ x,
                                float* __restrict__ resid,
                                __half* __restrict__ xf,
                                const float* __restrict__ w1a, const float* __restrict__ w1b,
                                const float* __restrict__ wxa, const float* __restrict__ wxb,
                                const float* __restrict__ woa, const float* __restrict__ wob,
                                __half* __restrict__ w1f,
                                __half* __restrict__ wxf,
                                __half* __restrict__ wof)
{
    const int NX = MROWS * DIM / 4;
    const int N1 = E2 * DM / 4;
    const int N2 = 64 * DI / 4;
    const int N3 = DM * DI / 4;
    const int NW = N1 + N2 + N3;
    int i = blockIdx.x * 256 + threadIdx.x;
    if (i < NX) {
        float4 v = reinterpret_cast<const float4*>(x)[i];
        reinterpret_cast<float4*>(resid)[i] = v;
        __half2* op = reinterpret_cast<__half2*>(xf) + 2 * i;
        op[0] = __floats2half2_rn(v.x, v.y);
        op[1] = __floats2half2_rn(v.z, v.w);
        return;
    }
    i -= NX;
    if (i >= 2 * NW) return;
    int dir = i / NW;
    i -= dir * NW;
    const float* w1 = dir ? w1b : w1a;
    const float* wx = dir ? wxb : wxa;
    const float* wo = dir ? wob : woa;
    if (i < N1) { half_body(w1, w1f + (long)dir * E2 * DM, i); return; }
    i -= N1;
    if (i < N2) { half_body(wx, wxf + (long)dir * 64 * DI, i); return; }
    i -= N2;
    half_body(wo, wof + (long)dir * DM * DI, i);
}

// ---------------- tensor-core NT GEMM, single fp16, ldmatrix + 3-stage cp.async ----
// Batched over blockIdx.z = dir*nks + kz. OUTH=1 emits __half, else fp32.
template<int BM, int BN, int WM, int WN, int OUTH>
__global__ void __launch_bounds__((BM / WM) * (BN / WN) * 32)
mma_gemm_kernel(const __half* __restrict__ A, const __half* __restrict__ B,
                void* __restrict__ Cv, int ksplit, int nks,
                int lda, long a_dstride, int acol0_step, int flip_is_dir,
                int ldb, long b_dstride,
                int ldc, long c_dstride, int ccol0_step, long csplit_stride)
{
    constexpr int THREADS = (BM / WM) * (BN / WN) * 32;
    constexpr int WM16 = WM / 16;
    constexpr int WN8  = WN / 8;

    __shared__ __align__(16) uint8_t As[3 * BM * 32];   // [stage][BM][32B]
    __shared__ __align__(16) uint8_t Bs[3 * BN * 32];

    const int tid  = threadIdx.x;
    const int bm0  = blockIdx.y * BM;
    const int bn0  = blockIdx.x * BN;
    const int z    = blockIdx.z;
    const int dir  = z / nks;
    const int kz   = z - dir * nks;
    const int kbeg = kz * ksplit;
    const int KT   = ksplit / 16;

    const __half* Ap = A + (long)dir * a_dstride;
    const __half* Bp = B + (long)dir * b_dstride;
    const int acol0 = dir * acol0_step;
    const int ccol0 = dir * ccol0_step;
    const int flip  = flip_is_dir ? dir : 0;
    char* Cb = (char*)Cv + ((long)dir * c_dstride + (long)kz * csplit_stride) * (OUTH ? 2 : 4);

    const int wid  = tid >> 5;
    const int lane = tid & 31;
    const int wm   = wid / (BN / WN);
    const int wn   = wid % (BN / WN);
    const int g    = lane >> 2;
    const int t    = lane & 3;

    float acc[WM16][WN8][4];
#pragma unroll
    for (int i = 0; i < WM16; i++)
#pragma unroll
        for (int j = 0; j < WN8; j++)
#pragma unroll
            for (int q = 0; q < 4; q++) acc[i][j][q] = 0.f;

    auto loadA = [&](int st, int k0) {
        for (int i = tid; i < BM * 2; i += THREADS) {
            int r = i >> 1;
            int c = i & 1;
            int mg = bm0 + r;
            int rowg = mg;
            if (flip) { int b = mg >> 11; int l = mg & 2047; rowg = (b << 11) + (2047 - l); }
            const __half* src = Ap + (long)rowg * lda + acol0 + k0 + c * 8;
            uint32_t dst = smem_u32(As + (st * BM + r) * 32 + ((c ^ ((r >> 2) & 1)) << 4));
            CPASYNC16(dst, src);
        }
    };
    auto loadB = [&](int st, int k0) {
        for (int i = tid; i < BN * 2; i += THREADS) {
            int r = i >> 1;
            int c = i & 1;
            const __half* src = Bp + (long)(bn0 + r) * ldb + k0 + c * 8;
            uint32_t dst = smem_u32(Bs + (st * BN + r) * 32 + ((c ^ ((r >> 2) & 1)) << 4));
            CPASYNC16(dst, src);
        }
    };

    const int a_tile   = lane >> 3;
    const int a_rowoff = ((a_tile & 1) << 3) + (lane & 7);
    const int a_chunk  = a_tile >> 1;
    const int b_rowoff = (((lane >> 4) & 1) << 3) + (lane & 7);
    const int b_chunk  = (lane >> 3) & 1;

    // prologue: stages 0 and 1
    loadA(0, kbeg); loadB(0, kbeg); CPCOMMIT();
    if (KT > 1) { loadA(1, kbeg + 16); loadB(1, kbeg + 16); }
    CPCOMMIT();

    for (int kt = 0; kt < KT; kt++) {
        CPWAIT1();
        __syncthreads();

        if (kt + 2 < KT) { loadA((kt + 2) % 3, kbeg + (kt + 2) * 16); loadB((kt + 2) % 3, kbeg + (kt + 2) * 16); }
        CPCOMMIT();

        const int st = kt % 3;
        const uint8_t* Ah = As + st * BM * 32;
        const uint8_t* Bh = Bs + st * BN * 32;

        uint32_t ah[WM16][4], bh[WN8][2];
#pragma unroll
        for (int i = 0; i < WM16; i++) {
            int r = wm * WM + i * 16 + a_rowoff;
            uint32_t off = r * 32 + (((a_chunk ^ ((r >> 2) & 1))) << 4);
            ldsm_x4(ah[i][0], ah[i][1], ah[i][2], ah[i][3], smem_u32(Ah + off));
        }
#pragma unroll
        for (int jp = 0; jp < WN8 / 2; jp++) {
            int r = wn * WN + jp * 16 + b_rowoff;
            uint32_t off = r * 32 + (((b_chunk ^ ((r >> 2) & 1))) << 4);
            ldsm_x4(bh[2 * jp][0], bh[2 * jp][1], bh[2 * jp + 1][0], bh[2 * jp + 1][1], smem_u32(Bh + off));
        }
#pragma unroll
        for (int i = 0; i < WM16; i++)
#pragma unroll
            for (int j = 0; j < WN8; j++)
                mma_f16(acc[i][j], ah[i], bh[j]);
    }

    // epilogue
#pragma unroll
    for (int i = 0; i < WM16; i++) {
#pragma unroll
        for (int j = 0; j < WN8; j++) {
            int r  = bm0 + wm * WM + i * 16 + g;
            int n0 = bn0 + ccol0 + wn * WN + j * 8 + 2 * t;
            if (OUTH) {
                __half2 h0 = __floats2half2_rn(acc[i][j][0], acc[i][j][1]);
                __half2 h1 = __floats2half2_rn(acc[i][j][2], acc[i][j][3]);
                *reinterpret_cast<__half2*>(Cb + ((long)r * ldc + n0) * 2)       = h0;
                *reinterpret_cast<__half2*>(Cb + ((long)(r + 8) * ldc + n0) * 2) = h1;
            } else {
                float2 v0 = make_float2(acc[i][j][0], acc[i][j][1]);
                float2 v1 = make_float2(acc[i][j][2], acc[i][j][3]);
                *reinterpret_cast<float2*>(Cb + ((long)r * ldc + n0) * 4)       = v0;
                *reinterpret_cast<float2*>(Cb + ((long)(r + 8) * ldc + n0) * 4) = v1;
            }
        }
    }
}

// ---------------- depthwise causal conv(4) + silu, fp16 in, fp32+fp16 out ----------
__global__ void conv_silu_kernel(const __half* __restrict__ xzf_base,
                                 const float* __restrict__ cwa, const float* __restrict__ cwb,
                                 const float* __restrict__ cba, const float* __restrict__ cbb,
                                 float* __restrict__ xc_base,
                                 __half* __restrict__ xcf_base)
{
    int c  = blockIdx.x * blockDim.x + threadIdx.x;   // channel in [0,DI)
    int l0 = blockIdx.y * 8;
    int zb = blockIdx.z;
    int dir = zb >> 1;
    int b   = zb & 1;

    const float* cw = dir ? cwb : cwa;
    const float* cb = dir ? cbb : cba;
    const __half* xz = xzf_base + (long)dir * MROWS * E2;
    float* xc = xc_base + (long)dir * MROWS * DI;
    __half* xcf = xcf_base + (long)dir * MROWS * DI;

    float w0 = cw[c * 4 + 0], w1 = cw[c * 4 + 1], w2 = cw[c * 4 + 2], w3 = cw[c * 4 + 3];
    float bias = cb[c];

    float v[11];
#pragma unroll
    for (int j = 0; j < 11; j++) {
        int l = l0 - 3 + j;
        v[j] = (l >= 0) ? __half2float(xz[(long)(b * LL + l) * E2 + c]) : 0.f;
    }
#pragma unroll
    for (int i = 0; i < 8; i++) {
        float a = v[i] * w0 + v[i + 1] * w1 + v[i + 2] * w2 + v[i + 3] * w3 + bias;
        float s = a / (1.f + __expf(-a));   // silu
        long idx = (long)(b * LL + l0 + i) * DI + c;
        xc[idx] = s;
        xcf[idx] = __float2half(s);
    }
}

// ---------------- delta = softplus(dt @ dt_w^T + dt_b), sums split-K inline --------
__global__ void delta_kernel(const float* __restrict__ part_base,
                             const float* __restrict__ dwa, const float* __restrict__ dwb,
                             const float* __restrict__ dba, const float* __restrict__ dbb,
                             float* __restrict__ delta_base)
{
    int d   = blockIdx.x * 256 + threadIdx.x;  // [0,DI)
    int m0  = blockIdx.y * 4;
    int dir = blockIdx.z;

    const float* dt_w = dir ? dwb : dwa;
    const float* dt_b = dir ? dbb : dba;
    const float* part = part_base + (long)dir * KSPLIT * M64;
    float* delta = delta_base + (long)dir * MROWS * DI;

    float w[DTR];
    const float4* w4 = reinterpret_cast<const float4*>(dt_w + (long)d * DTR);
#pragma unroll
    for (int r = 0; r < DTR / 4; r++) {
        float4 v = w4[r];
        w[4 * r + 0] = v.x; w[4 * r + 1] = v.y; w[4 * r + 2] = v.z; w[4 * r + 3] = v.w;
    }
    float bias = dt_b[d];

#pragma unroll
    for (int mi = 0; mi < 4; mi++) {
        long row = (long)(m0 + mi) * 64;
        float acc = bias;
#pragma unroll
        for (int r4 = 0; r4 < DTR / 4; r4++) {
            float4 a = *reinterpret_cast<const float4*>(part + row + 4 * r4);
#pragma unroll
            for (int zz = 1; zz < KSPLIT; zz++) {
                float4 bv = *reinterpret_cast<const float4*>(part + (long)zz * M64 + row + 4 * r4);
                a.x += bv.x; a.y += bv.y; a.z += bv.z; a.w += bv.w;
            }
            acc = fmaf(a.x, w[4 * r4 + 0], acc);
            acc = fmaf(a.y, w[4 * r4 + 1], acc);
            acc = fmaf(a.z, w[4 * r4 + 2], acc);
            acc = fmaf(a.w, w[4 * r4 + 3], acc);
        }
        float sp = (acc > 20.f) ? acc : log1pf(__expf(acc));
        delta[(long)(m0 + mi) * DI + d] = sp;
    }
}

// ---------------- scan pass1: chunk-local scan from h=0, batched -------------------
__global__ void scan_pass1_kernel(const float* __restrict__ delta_base,
                                  const float* __restrict__ xc_base,
                                  const float* __restrict__ part_base,
                                  const float* __restrict__ Aa_, const float* __restrict__ Ab_,
                                  float* __restrict__ cs_base,
                                  float* __restrict__ he_base)
{
    __shared__ float sB[LC][DS];
    int chunk = blockIdx.x;
    int d     = blockIdx.y * 256 + threadIdx.x;
    int zb    = blockIdx.z;
    int dir   = zb >> 1;
    int b     = zb & 1;
    int m0    = b * LL + chunk * LC;

    const float* A_log = dir ? Ab_ : Aa_;
    const float* delta = delta_base + (long)dir * MROWS * DI;
    const float* xc    = xc_base    + (long)dir * MROWS * DI;
    const float* part  = part_base  + (long)dir * KSPLIT * M64;
    float* cs = cs_base + (long)dir * BB * NC * DI;
    float* he = he_base + (long)dir * BB * NC * DI * DS;

    // stage B with inline split-K reduction
    for (int i = threadIdx.x; i < LC * DS; i += 256) {
        int tt = i >> 4, s = i & 15;
        long base = (long)(m0 + tt) * 64 + 32 + s;
        float v = part[base];
#pragma unroll
        for (int zz = 1; zz < KSPLIT; zz++) v += part[(long)zz * M64 + base];
        sB[tt][s] = v;
    }
    __syncthreads();

    float Aa[DS];
#pragma unroll
    for (int s = 0; s < DS; s++) Aa[s] = -__expf(A_log[d * DS + s]);
    float a0 = Aa[0];
    bool fast = true;
#pragma unroll
    for (int s = 1; s < DS; s++) fast = fast && (fabsf(Aa[s] - (s + 1) * a0) < 1e-4f * fabsf(Aa[s]));

    float h[DS];
#pragma unroll
    for (int s = 0; s < DS; s++) h[s] = 0.f;
    float S = 0.f;

    if (fast) {
        for (int tt = 0; tt < LC; tt++) {
            int m = m0 + tt;
            float dlt = delta[(long)m * DI + d];
            float xcv = xc[(long)m * DI + d];
            S += dlt;
            float du = dlt * xcv;
            float e1 = __expf(dlt * a0);
            float p = e1;
#pragma unroll
            for (int s = 0; s < DS; s++) {
                h[s] = fmaf(h[s], p, du * sB[tt][s]);
                p *= e1;
            }
        }
    } else {
        for (int tt = 0; tt < LC; tt++) {
            int m = m0 + tt;
            float dlt = delta[(long)m * DI + d];
            float xcv = xc[(long)m * DI + d];
            S += dlt;
            float du = dlt * xcv;
#pragma unroll
            for (int s = 0; s < DS; s++) {
                float da = __expf(dlt * Aa[s]);
                h[s] = fmaf(h[s], da, du * sB[tt][s]);
            }
        }
    }

    cs[(long)(b * NC + chunk) * DI + d] = S;
    float* hout = he + ((long)(b * NC + chunk) * DI + d) * DS;
#pragma unroll
    for (int s = 0; s < DS; s++) hout[s] = h[s];
}

// ---------------- scan fixup: sequential over the 16 chunks, batched ---------------
__global__ void scan_fixup_kernel(const float* __restrict__ cs_base,
                                  const float* __restrict__ he_base,
                                  const float* __restrict__ Aa_, const float* __restrict__ Ab_,
                                  float* __restrict__ hs_base)
{
    int idx = blockIdx.x * 256 + threadIdx.x;      // 2*BB*DI*DS threads
    int s = idx & 15;
    int d = (idx >> 4) & (DI - 1);
    int b = (idx >> 14) & 1;
    int dir = idx >> 15;

    const float* A_log = dir ? Ab_ : Aa_;
    const float* cs = cs_base + (long)dir * BB * NC * DI;
    const float* he = he_base + (long)dir * BB * NC * DI * DS;
    float* hs = hs_base + (long)dir * BB * NC * DI * DS;

    float A = -__expf(A_log[d * DS + s]);
    float h = 0.f;
    for (int c = 0; c < NC; c++) {
        long base = ((long)(b * NC + c) * DI + d) * DS + s;
        hs[base] = h;
        float S = cs[(long)(b * NC + c) * DI + d];
        h = __expf(A * S) * h + he[base];
    }
}

// ---------------- scan pass3: replay with h_start, emit gated y (fp16) -------------
__global__ void scan_pass3_kernel(const float* __restrict__ delta_base,
                                  const float* __restrict__ xc_base,
                                  const float* __restrict__ part_base,
                                  const float* __restrict__ Aa_, const float* __restrict__ Ab_,
                                  const float* __restrict__ hs_base,
                                  const float* __restrict__ Da_, const float* __restrict__ Db_,
                                  const __half* __restrict__ xzf_base,
                                  __half* __restrict__ ymf_base)
{
    __shared__ float sB[LC][DS];
    __shared__ float sC[LC][DS];
    int chunk = blockIdx.x;
    int d     = blockIdx.y * 256 + threadIdx.x;
    int zb    = blockIdx.z;
    int dir   = zb >> 1;
    int b     = zb & 1;
    int m0    = b * LL + chunk * LC;

    const float* A_log = dir ? Ab_ : Aa_;
    const float* Dp    = dir ? Db_ : Da_;
    const float* delta = delta_base + (long)dir * MROWS * DI;
    const float* xc    = xc_base    + (long)dir * MROWS * DI;
    const float* part  = part_base  + (long)dir * KSPLIT * M64;
    const float* hs    = hs_base    + (long)dir * BB * NC * DI * DS;
    const __half* xzf  = xzf_base   + (long)dir * MROWS * E2;
    __half* ymf = ymf_base + (long)dir * MROWS * DI;

    for (int i = threadIdx.x; i < LC * DS; i += 256) {
        int tt = i >> 4, s = i & 15;
        long baseB = (long)(m0 + tt) * 64 + 32 + s;
        long baseC = (long)(m0 + tt) * 64 + 48 + s;
        float vb = part[baseB], vc = part[baseC];
#pragma unroll
        for (int zz = 1; zz < KSPLIT; zz++) {
            vb += part[(long)zz * M64 + baseB];
            vc += part[(long)zz * M64 + baseC];
        }
        sB[tt][s] = vb;
        sC[tt][s] = vc;
    }
    __syncthreads();

    float Aa[DS];
#pragma unroll
    for (int s = 0; s < DS; s++) Aa[s] = -__expf(A_log[d * DS + s]);
    float a0 = Aa[0];
    bool fast = true;
#pragma unroll
    for (int s = 1; s < DS; s++) fast = fast && (fabsf(Aa[s] - (s + 1) * a0) < 1e-4f * fabsf(Aa[s]));

    float h[DS];
    const float* hin = hs + ((long)(b * NC + chunk) * DI + d) * DS;
#pragma unroll
    for (int s = 0; s < DS; s++) h[s] = hin[s];

    float Dv = Dp[d];

    for (int tt = 0; tt < LC; tt++) {
        int m = m0 + tt;
        float dlt = delta[(long)m * DI + d];
        float xcv = xc[(long)m * DI + d];
        float du = dlt * xcv;
        float y = 0.f;
        if (fast) {
            float e1 = __expf(dlt * a0);
            float p = e1;
#pragma unroll
            for (int s = 0; s < DS; s++) {
                h[s] = fmaf(h[s], p, du * sB[tt][s]);
                y = fmaf(h[s], sC[tt][s], y);
                p *= e1;
            }
        } else {
#pragma unroll
            for (int s = 0; s < DS; s++) {
                float da = __expf(dlt * Aa[s]);
                h[s] = fmaf(h[s], da, du * sB[tt][s]);
                y = fmaf(h[s], sC[tt][s], y);
            }
        }
        float z = __half2float(xzf[(long)m * E2 + DI + d]);
        float sil = z / (1.f + __expf(-z));
        float out = (y + xcv * Dv) * sil;
        ymf[(long)m * DI + d] = __float2half(out);
    }
}

// ---------------- host launcher ---------------------------------------------------
extern "C" void kernel_launch(void* const* d_in, const int* in_sizes, int n_in,
                              void* d_out, int out_size)
{
    const float* x = (const float*)d_in[0];
    float* out = (float*)d_out;

    float *xc, *part, *delta, *cs, *he, *hs;
    cudaGetSymbolAddress((void**)&xc,    g_xc);
    cudaGetSymbolAddress((void**)&part,  g_part);
    cudaGetSymbolAddress((void**)&delta, g_delta);
    cudaGetSymbolAddress((void**)&cs,    g_cs);
    cudaGetSymbolAddress((void**)&he,    g_he);
    cudaGetSymbolAddress((void**)&hs,    g_hs);

    __half *xf, *w1f, *wxf, *wof, *xzf, *xcf, *ymf;
    cudaGetSymbolAddress((void**)&xf,  g_xf);
    cudaGetSymbolAddress((void**)&w1f, g_w1f);
    cudaGetSymbolAddress((void**)&wxf, g_wxf);
    cudaGetSymbolAddress((void**)&wof, g_wof);
    cudaGetSymbolAddress((void**)&xzf, g_xzf);
    cudaGetSymbolAddress((void**)&xcf, g_xcf);
    cudaGetSymbolAddress((void**)&ymf, g_ymf);

    // per-direction input pointers
    const float* in_w[2];  const float* conv_w[2]; const float* conv_b[2];
    const float* xproj_w[2]; const float* dt_w[2]; const float* dt_b[2];
    const float* A_log[2]; const float* Dp[2];     const float* out_w[2];
    for (int dir = 0; dir < 2; dir++) {
        in_w[dir]    = (const float*)d_in[1 + dir * 9 + 0];
        conv_w[dir]  = (const float*)d_in[1 + dir * 9 + 1];
        conv_b[dir]  = (const float*)d_in[1 + dir * 9 + 2];
        xproj_w[dir] = (const float*)d_in[1 + dir * 9 + 3];
        dt_w[dir]    = (const float*)d_in[1 + dir * 9 + 4];
        dt_b[dir]    = (const float*)d_in[1 + dir * 9 + 5];
        A_log[dir]   = (const float*)d_in[1 + dir * 9 + 6];
        Dp[dir]      = (const float*)d_in[1 + dir * 9 + 7];
        out_w[dir]   = (const float*)d_in[1 + dir * 9 + 8];
    }

    const long HID = (long)MROWS * DIM;
    const int NTOT = (MROWS * DIM / 4) + 2 * ((E2 * DM / 4) + (64 * DI / 4) + (DM * DI / 4));

    // 1) fused prep: residual copy + x fp16 + all weights fp16
    prep_all_kernel<<<(NTOT + 255) / 256, 256>>>(
        x, out + HID, xf,
        in_w[0], in_w[1], xproj_w[0], xproj_w[1], out_w[0], out_w[1],
        w1f, wxf, wof);

    // 2) xz[dir] = x_dir @ in_w[dir]^T  (M=4096, N=2048, K=512), fp16 out
    mma_gemm_kernel<128, 128, 64, 32, 1><<<dim3(E2 / 128, MROWS / 128, 2), 256>>>(
        xf, w1f, xzf, DM, 1,
        /*lda*/ DIM, /*a_dstride*/ 0, /*acol0_step*/ DM, /*flip_is_dir*/ 1,
        /*ldb*/ DM, /*b_dstride*/ (long)E2 * DM,
        /*ldc*/ E2, /*c_dstride*/ (long)MROWS * E2, /*ccol0_step*/ 0, 0);

    // 3) conv + silu, both dirs (fp16 in, fp32 + fp16 out)
    conv_silu_kernel<<<dim3(DI / 256, LL / 8, 2 * BB), 256>>>(
        xzf, conv_w[0], conv_w[1], conv_b[0], conv_b[1], xc, xcf);

    // 4) part[dir][kz] = xc @ xproj_w^T  (split-K=4), fp32 partials; consumers reduce
    mma_gemm_kernel<64, 64, 32, 32, 0><<<dim3(1, MROWS / 64, 2 * KSPLIT), 128>>>(
        xcf, wxf, part, DI / KSPLIT, KSPLIT,
        DI, (long)MROWS * DI, 0, 0,
        DI, (long)64 * DI,
        64, (long)KSPLIT * M64, 0, (long)M64);

    // 5) delta, both dirs (sums partials inline)
    delta_kernel<<<dim3(DI / 256, MROWS / 4, 2), 256>>>(
        part, dt_w[0], dt_w[1], dt_b[0], dt_b[1], delta);

    // 6-8) chunked parallel scan, both dirs (stage B/C with inline reduction)
    scan_pass1_kernel<<<dim3(NC, DI / 256, 2 * BB), 256>>>(
        delta, xc, part, A_log[0], A_log[1], cs, he);
    scan_fixup_kernel<<<(2 * BB * DI * DS) / 256, 256>>>(
        cs, he, A_log[0], A_log[1], hs);
    scan_pass3_kernel<<<dim3(NC, DI / 256, 2 * BB), 256>>>(
        delta, xc, part, A_log[0], A_log[1], hs, Dp[0], Dp[1], xzf, ymf);

    // 9) hidden[:, :, dir*512:+512] = ym @ out_w^T  (M=4096, N=512, K=1024), fp32 out
    mma_gemm_kernel<128, 128, 64, 32, 0><<<dim3(DM / 128, MROWS / 128, 2), 256>>>(
        ymf, wof, out, DI, 1,
        DI, (long)MROWS * DI, 0, 0,
        DI, (long)DM * DI,
        DIM, 0, DM, 0);
}

// round 9
// speedup vs baseline: 1.1868x; 1.1868x over previous
#include <cuda_runtime.h>
#include <cuda_bf16.h>
#include <cuda_fp16.h>
#include <cstdint>

// Problem constants
#define BB    2
#define LL    2048
#define DIM   1024
#define DM    512
#define DI    1024
#define E2    2048      // 2*DI
#define MROWS 4096      // BB*LL
#define DS    16        // D_STATE
#define DTR   32        // DT_RANK
#define NC    16        // scan chunks
#define LC    128       // chunk length (NC*LC == LL)
#define KSPLIT 4        // split-K factor for xproj GEMM
#define M64   (MROWS * 64)

// ---------------- scratch (static device memory; no allocation allowed) ----------
__device__ float g_xc   [2][MROWS * DI];         // conv+silu output (fp32 for scan)
__device__ float g_part [2][KSPLIT][M64];        // split-K partials for xproj
__device__ float g_dbc  [2][M64];                // reduced x-proj output (dt|B|C)
__device__ float g_delta[2][MROWS * DI];         // softplus(dt @ dt_w^T + dt_b)
__device__ float g_cs   [2][BB * NC * DI];       // per-chunk sum of delta
__device__ float g_he   [2][BB * NC * DI * DS];  // chunk-local h_end
__device__ float g_hs   [2][BB * NC * DI * DS];  // chunk h_start (after fixup)

// fp16 operands (all GEMMs single-fp16)
__device__ __half g_xf  [MROWS * DIM];           // x
__device__ __half g_w1f [2][E2 * DM];            // in_w
__device__ __half g_wxf [2][64 * DI];            // xproj_w
__device__ __half g_wof [2][DM * DI];            // out_w
__device__ __half g_xzf [2][MROWS * E2];         // in-proj output (xh | z), fp16
__device__ __half g_xcf [2][MROWS * DI];         // conv output fp16 (xproj A operand)
__device__ __half g_ymf [2][MROWS * DI];         // scan output fp16 (GEMM3 A operand)

// ---------------- helpers ----------------------------------------------------------
__device__ __forceinline__ void mma_f16(float* c, const uint32_t* a, const uint32_t* b) {
    asm volatile(
        "mma.sync.aligned.m16n8k16.row.col.f32.f16.f16.f32 "
        "{%0,%1,%2,%3}, {%4,%5,%6,%7}, {%8,%9}, {%0,%1,%2,%3};\n"
        : "+f"(c[0]), "+f"(c[1]), "+f"(c[2]), "+f"(c[3])
        : "r"(a[0]), "r"(a[1]), "r"(a[2]), "r"(a[3]), "r"(b[0]), "r"(b[1]));
}

__device__ __forceinline__ void ldsm_x4(uint32_t& r0, uint32_t& r1, uint32_t& r2, uint32_t& r3, uint32_t a) {
    asm volatile("ldmatrix.sync.aligned.m8n8.x4.shared.b16 {%0,%1,%2,%3}, [%4];"
                 : "=r"(r0), "=r"(r1), "=r"(r2), "=r"(r3) : "r"(a));
}

#define CPASYNC16(dst, src) asm volatile("cp.async.cg.shared.global [%0], [%1], 16;\n" :: "r"(dst), "l"(src))
#define CPCOMMIT()          asm volatile("cp.async.commit_group;\n")
#define CPWAIT1()           asm volatile("cp.async.wait_group 1;\n")

__device__ __forceinline__ uint32_t smem_u32(const void* p) {
    return (uint32_t)__cvta_generic_to_shared(p);
}

__device__ __forceinline__ void half_body(const float* __restrict__ in,
                                          __half* __restrict__ o, int i)
{
    float4 v = reinterpret_cast<const float4*>(in)[i];
    __half2* op = reinterpret_cast<__half2*>(o) + 2 * i;
    op[0] = __floats2half2_rn(v.x, v.y);
    op[1] = __floats2half2_rn(v.z, v.w);
}

// ---------------- prep: residual copy + x fp16 + all weight fp16, ONE launch -------
__global__ void prep_all_kernel(const float* __restrict__ x,
                                float* __restrict__ resid,
                                __half* __restrict__ xf,
                                const float* __restrict__ w1a, const float* __restrict__ w1b,
                                const float* __restrict__ wxa, const float* __restrict__ wxb,
                                const float* __restrict__ woa, const float* __restrict__ wob,
                                __half* __restrict__ w1f,
                                __half* __restrict__ wxf,
                                __half* __restrict__ wof)
{
    const int NX = MROWS * DIM / 4;
    const int N1 = E2 * DM / 4;
    const int N2 = 64 * DI / 4;
    const int N3 = DM * DI / 4;
    const int NW = N1 + N2 + N3;
    int i = blockIdx.x * 256 + threadIdx.x;
    if (i < NX) {
        float4 v = reinterpret_cast<const float4*>(x)[i];
        reinterpret_cast<float4*>(resid)[i] = v;
        __half2* op = reinterpret_cast<__half2*>(xf) + 2 * i;
        op[0] = __floats2half2_rn(v.x, v.y);
        op[1] = __floats2half2_rn(v.z, v.w);
        return;
    }
    i -= NX;
    if (i >= 2 * NW) return;
    int dir = i / NW;
    i -= dir * NW;
    const float* w1 = dir ? w1b : w1a;
    const float* wx = dir ? wxb : wxa;
    const float* wo = dir ? wob : woa;
    if (i < N1) { half_body(w1, w1f + (long)dir * E2 * DM, i); return; }
    i -= N1;
    if (i < N2) { half_body(wx, wxf + (long)dir * 64 * DI, i); return; }
    i -= N2;
    half_body(wo, wof + (long)dir * DM * DI, i);
}

// ---------------- tensor-core NT GEMM, single fp16, ldmatrix + 3-stage cp.async ----
// Batched over blockIdx.z = dir*nks + kz. OUTH=1 emits __half, else fp32.
template<int BM, int BN, int WM, int WN, int OUTH>
__global__ void __launch_bounds__((BM / WM) * (BN / WN) * 32)
mma_gemm_kernel(const __half* __restrict__ A, const __half* __restrict__ B,
                void* __restrict__ Cv, int ksplit, int nks,
                int lda, long a_dstride, int acol0_step, int flip_is_dir,
                int ldb, long b_dstride,
                int ldc, long c_dstride, int ccol0_step, long csplit_stride)
{
    constexpr int THREADS = (BM / WM) * (BN / WN) * 32;
    constexpr int WM16 = WM / 16;
    constexpr int WN8  = WN / 8;

    __shared__ __align__(16) uint8_t As[3 * BM * 32];   // [stage][BM][32B]
    __shared__ __align__(16) uint8_t Bs[3 * BN * 32];

    const int tid  = threadIdx.x;
    const int bm0  = blockIdx.y * BM;
    const int bn0  = blockIdx.x * BN;
    const int z    = blockIdx.z;
    const int dir  = z / nks;
    const int kz   = z - dir * nks;
    const int kbeg = kz * ksplit;
    const int KT   = ksplit / 16;

    const __half* Ap = A + (long)dir * a_dstride;
    const __half* Bp = B + (long)dir * b_dstride;
    const int acol0 = dir * acol0_step;
    const int ccol0 = dir * ccol0_step;
    const int flip  = flip_is_dir ? dir : 0;
    char* Cb = (char*)Cv + ((long)dir * c_dstride + (long)kz * csplit_stride) * (OUTH ? 2 : 4);

    const int wid  = tid >> 5;
    const int lane = tid & 31;
    const int wm   = wid / (BN / WN);
    const int wn   = wid % (BN / WN);
    const int g    = lane >> 2;
    const int t    = lane & 3;

    float acc[WM16][WN8][4];
#pragma unroll
    for (int i = 0; i < WM16; i++)
#pragma unroll
        for (int j = 0; j < WN8; j++)
#pragma unroll
            for (int q = 0; q < 4; q++) acc[i][j][q] = 0.f;

    auto loadA = [&](int st, int k0) {
        for (int i = tid; i < BM * 2; i += THREADS) {
            int r = i >> 1;
            int c = i & 1;
            int mg = bm0 + r;
            int rowg = mg;
            if (flip) { int b = mg >> 11; int l = mg & 2047; rowg = (b << 11) + (2047 - l); }
            const __half* src = Ap + (long)rowg * lda + acol0 + k0 + c * 8;
            uint32_t dst = smem_u32(As + (st * BM + r) * 32 + ((c ^ ((r >> 2) & 1)) << 4));
            CPASYNC16(dst, src);
        }
    };
    auto loadB = [&](int st, int k0) {
        for (int i = tid; i < BN * 2; i += THREADS) {
            int r = i >> 1;
            int c = i & 1;
            const __half* src = Bp + (long)(bn0 + r) * ldb + k0 + c * 8;
            uint32_t dst = smem_u32(Bs + (st * BN + r) * 32 + ((c ^ ((r >> 2) & 1)) << 4));
            CPASYNC16(dst, src);
        }
    };

    const int a_tile   = lane >> 3;
    const int a_rowoff = ((a_tile & 1) << 3) + (lane & 7);
    const int a_chunk  = a_tile >> 1;
    const int b_rowoff = (((lane >> 4) & 1) << 3) + (lane & 7);
    const int b_chunk  = (lane >> 3) & 1;

    // prologue: stages 0 and 1
    loadA(0, kbeg); loadB(0, kbeg); CPCOMMIT();
    if (KT > 1) { loadA(1, kbeg + 16); loadB(1, kbeg + 16); }
    CPCOMMIT();

    for (int kt = 0; kt < KT; kt++) {
        CPWAIT1();
        __syncthreads();

        if (kt + 2 < KT) { loadA((kt + 2) % 3, kbeg + (kt + 2) * 16); loadB((kt + 2) % 3, kbeg + (kt + 2) * 16); }
        CPCOMMIT();

        const int st = kt % 3;
        const uint8_t* Ah = As + st * BM * 32;
        const uint8_t* Bh = Bs + st * BN * 32;

        uint32_t ah[WM16][4], bh[WN8][2];
#pragma unroll
        for (int i = 0; i < WM16; i++) {
            int r = wm * WM + i * 16 + a_rowoff;
            uint32_t off = r * 32 + (((a_chunk ^ ((r >> 2) & 1))) << 4);
            ldsm_x4(ah[i][0], ah[i][1], ah[i][2], ah[i][3], smem_u32(Ah + off));
        }
#pragma unroll
        for (int jp = 0; jp < WN8 / 2; jp++) {
            int r = wn * WN + jp * 16 + b_rowoff;
            uint32_t off = r * 32 + (((b_chunk ^ ((r >> 2) & 1))) << 4);
            ldsm_x4(bh[2 * jp][0], bh[2 * jp][1], bh[2 * jp + 1][0], bh[2 * jp + 1][1], smem_u32(Bh + off));
        }
#pragma unroll
        for (int i = 0; i < WM16; i++)
#pragma unroll
            for (int j = 0; j < WN8; j++)
                mma_f16(acc[i][j], ah[i], bh[j]);
    }

    // epilogue
#pragma unroll
    for (int i = 0; i < WM16; i++) {
#pragma unroll
        for (int j = 0; j < WN8; j++) {
            int r  = bm0 + wm * WM + i * 16 + g;
            int n0 = bn0 + ccol0 + wn * WN + j * 8 + 2 * t;
            if (OUTH) {
                __half2 h0 = __floats2half2_rn(acc[i][j][0], acc[i][j][1]);
                __half2 h1 = __floats2half2_rn(acc[i][j][2], acc[i][j][3]);
                *reinterpret_cast<__half2*>(Cb + ((long)r * ldc + n0) * 2)       = h0;
                *reinterpret_cast<__half2*>(Cb + ((long)(r + 8) * ldc + n0) * 2) = h1;
            } else {
                float2 v0 = make_float2(acc[i][j][0], acc[i][j][1]);
                float2 v1 = make_float2(acc[i][j][2], acc[i][j][3]);
                *reinterpret_cast<float2*>(Cb + ((long)r * ldc + n0) * 4)       = v0;
                *reinterpret_cast<float2*>(Cb + ((long)(r + 8) * ldc + n0) * 4) = v1;
            }
        }
    }
}

// ---------------- split-K reduction: dbc[dir] = sum_z part[dir][z], both dirs ------
__global__ void reduce_partials_kernel(const float* __restrict__ part, float* __restrict__ dbc)
{
    const int n4 = M64 / 4;                    // per-dir float4 count
    int i = blockIdx.x * 256 + threadIdx.x;    // over 2*n4
    if (i >= 2 * n4) return;
    int dir = i / n4;
    int j = i - dir * n4;
    const float* p = part + (long)dir * KSPLIT * M64;
    float4 a = reinterpret_cast<const float4*>(p)[j];
#pragma unroll
    for (int z = 1; z < KSPLIT; z++) {
        float4 b = reinterpret_cast<const float4*>(p + (long)z * M64)[j];
        a.x += b.x; a.y += b.y; a.z += b.z; a.w += b.w;
    }
    reinterpret_cast<float4*>(dbc + (long)dir * M64)[j] = a;
}

// ---------------- depthwise causal conv(4) + silu, fp16 in, fp32+fp16 out ----------
__global__ void conv_silu_kernel(const __half* __restrict__ xzf_base,
                                 const float* __restrict__ cwa, const float* __restrict__ cwb,
                                 const float* __restrict__ cba, const float* __restrict__ cbb,
                                 float* __restrict__ xc_base,
                                 __half* __restrict__ xcf_base)
{
    int c  = blockIdx.x * blockDim.x + threadIdx.x;   // channel in [0,DI)
    int l0 = blockIdx.y * 8;
    int zb = blockIdx.z;
    int dir = zb >> 1;
    int b   = zb & 1;

    const float* cw = dir ? cwb : cwa;
    const float* cb = dir ? cbb : cba;
    const __half* xz = xzf_base + (long)dir * MROWS * E2;
    float* xc = xc_base + (long)dir * MROWS * DI;
    __half* xcf = xcf_base + (long)dir * MROWS * DI;

    float w0 = cw[c * 4 + 0], w1 = cw[c * 4 + 1], w2 = cw[c * 4 + 2], w3 = cw[c * 4 + 3];
    float bias = cb[c];

    float v[11];
#pragma unroll
    for (int j = 0; j < 11; j++) {
        int l = l0 - 3 + j;
        v[j] = (l >= 0) ? __half2float(xz[(long)(b * LL + l) * E2 + c]) : 0.f;
    }
#pragma unroll
    for (int i = 0; i < 8; i++) {
        float a = v[i] * w0 + v[i + 1] * w1 + v[i + 2] * w2 + v[i + 3] * w3 + bias;
        float s = a / (1.f + __expf(-a));   // silu
        long idx = (long)(b * LL + l0 + i) * DI + c;
        xc[idx] = s;
        xcf[idx] = __float2half(s);
    }
}

// ---------------- delta = softplus(dt @ dt_w^T + dt_b), batched --------------------
__global__ void delta_kernel(const float* __restrict__ dbc_base,
                             const float* __restrict__ dwa, const float* __restrict__ dwb,
                             const float* __restrict__ dba, const float* __restrict__ dbb,
                             float* __restrict__ delta_base)
{
    int d   = blockIdx.x * 256 + threadIdx.x;  // [0,DI)
    int m0  = blockIdx.y * 4;
    int dir = blockIdx.z;

    const float* dt_w = dir ? dwb : dwa;
    const float* dt_b = dir ? dbb : dba;
    const float* dbc = dbc_base + (long)dir * M64;
    float* delta = delta_base + (long)dir * MROWS * DI;

    float w[DTR];
    const float4* w4 = reinterpret_cast<const float4*>(dt_w + (long)d * DTR);
#pragma unroll
    for (int r = 0; r < DTR / 4; r++) {
        float4 v = w4[r];
        w[4 * r + 0] = v.x; w[4 * r + 1] = v.y; w[4 * r + 2] = v.z; w[4 * r + 3] = v.w;
    }
    float bias = dt_b[d];

#pragma unroll
    for (int mi = 0; mi < 4; mi++) {
        const float* row = dbc + (long)(m0 + mi) * 64;
        float acc = bias;
#pragma unroll
        for (int r = 0; r < DTR; r++) acc = fmaf(row[r], w[r], acc);
        float sp = (acc > 20.f) ? acc : log1pf(__expf(acc));
        delta[(long)(m0 + mi) * DI + d] = sp;
    }
}

// ---------------- scan pass1: chunk-local scan from h=0, batched -------------------
__global__ void scan_pass1_kernel(const float* __restrict__ delta_base,
                                  const float* __restrict__ xc_base,
                                  const float* __restrict__ dbc_base,
                                  const float* __restrict__ Aa_, const float* __restrict__ Ab_,
                                  float* __restrict__ cs_base,
                                  float* __restrict__ he_base)
{
    __shared__ float sB[LC][DS];
    int chunk = blockIdx.x;
    int d     = blockIdx.y * 256 + threadIdx.x;
    int zb    = blockIdx.z;
    int dir   = zb >> 1;
    int b     = zb & 1;
    int m0    = b * LL + chunk * LC;

    const float* A_log = dir ? Ab_ : Aa_;
    const float* delta = delta_base + (long)dir * MROWS * DI;
    const float* xc    = xc_base    + (long)dir * MROWS * DI;
    const float* dbc   = dbc_base   + (long)dir * M64;
    float* cs = cs_base + (long)dir * BB * NC * DI;
    float* he = he_base + (long)dir * BB * NC * DI * DS;

    const float* dbc0 = dbc + (long)m0 * 64;
    for (int i = threadIdx.x; i < LC * DS; i += 256) {
        int tt = i >> 4, s = i & 15;
        sB[tt][s] = dbc0[tt * 64 + 32 + s];
    }
    __syncthreads();

    float Aa[DS];
#pragma unroll
    for (int s = 0; s < DS; s++) Aa[s] = -__expf(A_log[d * DS + s]);
    float a0 = Aa[0];
    bool fast = true;
#pragma unroll
    for (int s = 1; s < DS; s++) fast = fast && (fabsf(Aa[s] - (s + 1) * a0) < 1e-4f * fabsf(Aa[s]));

    float h[DS];
#pragma unroll
    for (int s = 0; s < DS; s++) h[s] = 0.f;
    float S = 0.f;

    if (fast) {
        for (int tt = 0; tt < LC; tt++) {
            int m = m0 + tt;
            float dlt = delta[(long)m * DI + d];
            float xcv = xc[(long)m * DI + d];
            S += dlt;
            float du = dlt * xcv;
            float e1 = __expf(dlt * a0);
            float p = e1;
#pragma unroll
            for (int s = 0; s < DS; s++) {
                h[s] = fmaf(h[s], p, du * sB[tt][s]);
                p *= e1;
            }
        }
    } else {
        for (int tt = 0; tt < LC; tt++) {
            int m = m0 + tt;
            float dlt = delta[(long)m * DI + d];
            float xcv = xc[(long)m * DI + d];
            S += dlt;
            float du = dlt * xcv;
#pragma unroll
            for (int s = 0; s < DS; s++) {
                float da = __expf(dlt * Aa[s]);
                h[s] = fmaf(h[s], da, du * sB[tt][s]);
            }
        }
    }

    cs[(long)(b * NC + chunk) * DI + d] = S;
    float* hout = he + ((long)(b * NC + chunk) * DI + d) * DS;
#pragma unroll
    for (int s = 0; s < DS; s++) hout[s] = h[s];
}

// ---------------- scan fixup: sequential over the 16 chunks, batched ---------------
__global__ void scan_fixup_kernel(const float* __restrict__ cs_base,
                                  const float* __restrict__ he_base,
                                  const float* __restrict__ Aa_, const float* __restrict__ Ab_,
                                  float* __restrict__ hs_base)
{
    int idx = blockIdx.x * 256 + threadIdx.x;      // 2*BB*DI*DS threads
    int s = idx & 15;
    int d = (idx >> 4) & (DI - 1);
    int b = (idx >> 14) & 1;
    int dir = idx >> 15;

    const float* A_log = dir ? Ab_ : Aa_;
    const float* cs = cs_base + (long)dir * BB * NC * DI;
    const float* he = he_base + (long)dir * BB * NC * DI * DS;
    float* hs = hs_base + (long)dir * BB * NC * DI * DS;

    float A = -__expf(A_log[d * DS + s]);
    float h = 0.f;
    for (int c = 0; c < NC; c++) {
        long base = ((long)(b * NC + c) * DI + d) * DS + s;
        hs[base] = h;
        float S = cs[(long)(b * NC + c) * DI + d];
        h = __expf(A * S) * h + he[base];
    }
}

// ---------------- scan pass3: replay with h_start, emit gated y (fp16) -------------
__global__ void scan_pass3_kernel(const float* __restrict__ delta_base,
                                  const float* __restrict__ xc_base,
                                  const float* __restrict__ dbc_base,
                                  const float* __restrict__ Aa_, const float* __restrict__ Ab_,
                                  const float* __restrict__ hs_base,
                                  const float* __restrict__ Da_, const float* __restrict__ Db_,
                                  const __half* __restrict__ xzf_base,
                                  __half* __restrict__ ymf_base)
{
    __shared__ float sB[LC][DS];
    __shared__ float sC[LC][DS];
    int chunk = blockIdx.x;
    int d     = blockIdx.y * 256 + threadIdx.x;
    int zb    = blockIdx.z;
    int dir   = zb >> 1;
    int b     = zb & 1;
    int m0    = b * LL + chunk * LC;

    const float* A_log = dir ? Ab_ : Aa_;
    const float* Dp    = dir ? Db_ : Da_;
    const float* delta = delta_base + (long)dir * MROWS * DI;
    const float* xc    = xc_base    + (long)dir * MROWS * DI;
    const float* dbc   = dbc_base   + (long)dir * M64;
    const float* hs    = hs_base    + (long)dir * BB * NC * DI * DS;
    const __half* xzf  = xzf_base   + (long)dir * MROWS * E2;
    __half* ymf = ymf_base + (long)dir * MROWS * DI;

    const float* dbc0 = dbc + (long)m0 * 64;
    for (int i = threadIdx.x; i < LC * DS; i += 256) {
        int tt = i >> 4, s = i & 15;
        sB[tt][s] = dbc0[tt * 64 + 32 + s];
        sC[tt][s] = dbc0[tt * 64 + 48 + s];
    }
    __syncthreads();

    float Aa[DS];
#pragma unroll
    for (int s = 0; s < DS; s++) Aa[s] = -__expf(A_log[d * DS + s]);
    float a0 = Aa[0];
    bool fast = true;
#pragma unroll
    for (int s = 1; s < DS; s++) fast = fast && (fabsf(Aa[s] - (s + 1) * a0) < 1e-4f * fabsf(Aa[s]));

    float h[DS];
    const float* hin = hs + ((long)(b * NC + chunk) * DI + d) * DS;
#pragma unroll
    for (int s = 0; s < DS; s++) h[s] = hin[s];

    float Dv = Dp[d];

    for (int tt = 0; tt < LC; tt++) {
        int m = m0 + tt;
        float dlt = delta[(long)m * DI + d];
        float xcv = xc[(long)m * DI + d];
        float du = dlt * xcv;
        float y = 0.f;
        if (fast) {
            float e1 = __expf(dlt * a0);
            float p = e1;
#pragma unroll
            for (int s = 0; s < DS; s++) {
                h[s] = fmaf(h[s], p, du * sB[tt][s]);
                y = fmaf(h[s], sC[tt][s], y);
                p *= e1;
            }
        } else {
#pragma unroll
            for (int s = 0; s < DS; s++) {
                float da = __expf(dlt * Aa[s]);
                h[s] = fmaf(h[s], da, du * sB[tt][s]);
                y = fmaf(h[s], sC[tt][s], y);
            }
        }
        float z = __half2float(xzf[(long)m * E2 + DI + d]);
        float sil = z / (1.f + __expf(-z));
        float out = (y + xcv * Dv) * sil;
        ymf[(long)m * DI + d] = __float2half(out);
    }
}

// ---------------- host launcher ---------------------------------------------------
extern "C" void kernel_launch(void* const* d_in, const int* in_sizes, int n_in,
                              void* d_out, int out_size)
{
    const float* x = (const float*)d_in[0];
    float* out = (float*)d_out;

    float *xc, *part, *dbc, *delta, *cs, *he, *hs;
    cudaGetSymbolAddress((void**)&xc,    g_xc);
    cudaGetSymbolAddress((void**)&part,  g_part);
    cudaGetSymbolAddress((void**)&dbc,   g_dbc);
    cudaGetSymbolAddress((void**)&delta, g_delta);
    cudaGetSymbolAddress((void**)&cs,    g_cs);
    cudaGetSymbolAddress((void**)&he,    g_he);
    cudaGetSymbolAddress((void**)&hs,    g_hs);

    __half *xf, *w1f, *wxf, *wof, *xzf, *xcf, *ymf;
    cudaGetSymbolAddress((void**)&xf,  g_xf);
    cudaGetSymbolAddress((void**)&w1f, g_w1f);
    cudaGetSymbolAddress((void**)&wxf, g_wxf);
    cudaGetSymbolAddress((void**)&wof, g_wof);
    cudaGetSymbolAddress((void**)&xzf, g_xzf);
    cudaGetSymbolAddress((void**)&xcf, g_xcf);
    cudaGetSymbolAddress((void**)&ymf, g_ymf);

    // per-direction input pointers
    const float* in_w[2];  const float* conv_w[2]; const float* conv_b[2];
    const float* xproj_w[2]; const float* dt_w[2]; const float* dt_b[2];
    const float* A_log[2]; const float* Dp[2];     const float* out_w[2];
    for (int dir = 0; dir < 2; dir++) {
        in_w[dir]    = (const float*)d_in[1 + dir * 9 + 0];
        conv_w[dir]  = (const float*)d_in[1 + dir * 9 + 1];
        conv_b[dir]  = (const float*)d_in[1 + dir * 9 + 2];
        xproj_w[dir] = (const float*)d_in[1 + dir * 9 + 3];
        dt_w[dir]    = (const float*)d_in[1 + dir * 9 + 4];
        dt_b[dir]    = (const float*)d_in[1 + dir * 9 + 5];
        A_log[dir]   = (const float*)d_in[1 + dir * 9 + 6];
        Dp[dir]      = (const float*)d_in[1 + dir * 9 + 7];
        out_w[dir]   = (const float*)d_in[1 + dir * 9 + 8];
    }

    const long HID = (long)MROWS * DIM;
    const int NTOT = (MROWS * DIM / 4) + 2 * ((E2 * DM / 4) + (64 * DI / 4) + (DM * DI / 4));

    // 1) fused prep: residual copy + x fp16 + all weights fp16
    prep_all_kernel<<<(NTOT + 255) / 256, 256>>>(
        x, out + HID, xf,
        in_w[0], in_w[1], xproj_w[0], xproj_w[1], out_w[0], out_w[1],
        w1f, wxf, wof);

    // 2) xz[dir] = x_dir @ in_w[dir]^T  (M=4096, N=2048, K=512), fp16 out
    mma_gemm_kernel<128, 128, 64, 32, 1><<<dim3(E2 / 128, MROWS / 128, 2), 256>>>(
        xf, w1f, xzf, DM, 1,
        /*lda*/ DIM, /*a_dstride*/ 0, /*acol0_step*/ DM, /*flip_is_dir*/ 1,
        /*ldb*/ DM, /*b_dstride*/ (long)E2 * DM,
        /*ldc*/ E2, /*c_dstride*/ (long)MROWS * E2, /*ccol0_step*/ 0, 0);

    // 3) conv + silu, both dirs (fp16 in, fp32 + fp16 out)
    conv_silu_kernel<<<dim3(DI / 256, LL / 8, 2 * BB), 256>>>(
        xzf, conv_w[0], conv_w[1], conv_b[0], conv_b[1], xc, xcf);

    // 4) part[dir][kz] = xc @ xproj_w^T  (split-K=4), then compact reduce -> dbc
    mma_gemm_kernel<64, 64, 32, 32, 0><<<dim3(1, MROWS / 64, 2 * KSPLIT), 128>>>(
        xcf, wxf, part, DI / KSPLIT, KSPLIT,
        DI, (long)MROWS * DI, 0, 0,
        DI, (long)64 * DI,
        64, (long)KSPLIT * M64, 0, (long)M64);
    reduce_partials_kernel<<<(2 * M64 / 4 + 255) / 256, 256>>>(part, dbc);

    // 5) delta, both dirs (reads compact dbc)
    delta_kernel<<<dim3(DI / 256, MROWS / 4, 2), 256>>>(
        dbc, dt_w[0], dt_w[1], dt_b[0], dt_b[1], delta);

    // 6-8) chunked parallel scan, both dirs (reads compact dbc)
    scan_pass1_kernel<<<dim3(NC, DI / 256, 2 * BB), 256>>>(
        delta, xc, dbc, A_log[0], A_log[1], cs, he);
    scan_fixup_kernel<<<(2 * BB * DI * DS) / 256, 256>>>(
        cs, he, A_log[0], A_log[1], hs);
    scan_pass3_kernel<<<dim3(NC, DI / 256, 2 * BB), 256>>>(
        delta, xc, dbc, A_log[0], A_log[1], hs, Dp[0], Dp[1], xzf, ymf);

    // 9) hidden[:, :, dir*512:+512] = ym @ out_w^T  (M=4096, N=512, K=1024), fp32 out
    mma_gemm_kernel<128, 128, 64, 32, 0><<<dim3(DM / 128, MROWS / 128, 2), 256>>>(
        ymf, wof, out, DI, 1,
        DI, (long)MROWS * DI, 0, 0,
        DI, (long)DM * DI,
        DIM, 0, DM, 0);
}

// round 10
// speedup vs baseline: 1.3220x; 1.1139x over previous
#include <cuda_runtime.h>
#include <cuda_bf16.h>
#include <cuda_fp16.h>
#include <cstdint>

// Problem constants
#define BB    2
#define LL    2048
#define DIM   1024
#define DM    512
#define DI    1024
#define E2    2048      // 2*DI
#define MROWS 4096      // BB*LL
#define DS    16        // D_STATE
#define DTR   32        // DT_RANK
#define NC    16        // scan chunks
#define LC    128       // chunk length (NC*LC == LL)
#define KSPLIT 4        // split-K factor for xproj GEMM
#define M64   (MROWS * 64)

// ---------------- scratch (static device memory; no allocation allowed) ----------
__device__ float g_part [2][KSPLIT][M64];        // split-K partials for xproj
__device__ float g_dbc  [2][M64];                // reduced x-proj output (dt|B|C)
__device__ float g_cs   [2][BB * NC * DI];       // per-chunk sum of delta
__device__ float g_he   [2][BB * NC * DI * DS];  // chunk-local h_end
__device__ float g_hs   [2][BB * NC * DI * DS];  // chunk h_start (after fixup)

// fp16 operands / streams
__device__ __half g_xf   [MROWS * DIM];          // x
__device__ __half g_w1f  [2][E2 * DM];           // in_w
__device__ __half g_wxf  [2][64 * DI];           // xproj_w
__device__ __half g_wof  [2][DM * DI];           // out_w
__device__ __half g_xzf  [2][MROWS * E2];        // in-proj output (xh | z)
__device__ __half g_xcf  [2][MROWS * DI];        // conv output (xproj A operand + scan)
__device__ __half g_dltf [2][MROWS * DI];        // delta (fp16 scan stream)
__device__ __half g_ymf  [2][MROWS * DI];        // scan output (GEMM3 A operand)

// ---------------- helpers ----------------------------------------------------------
__device__ __forceinline__ void mma_f16(float* c, const uint32_t* a, const uint32_t* b) {
    asm volatile(
        "mma.sync.aligned.m16n8k16.row.col.f32.f16.f16.f32 "
        "{%0,%1,%2,%3}, {%4,%5,%6,%7}, {%8,%9}, {%0,%1,%2,%3};\n"
        : "+f"(c[0]), "+f"(c[1]), "+f"(c[2]), "+f"(c[3])
        : "r"(a[0]), "r"(a[1]), "r"(a[2]), "r"(a[3]), "r"(b[0]), "r"(b[1]));
}

__device__ __forceinline__ void ldsm_x4(uint32_t& r0, uint32_t& r1, uint32_t& r2, uint32_t& r3, uint32_t a) {
    asm volatile("ldmatrix.sync.aligned.m8n8.x4.shared.b16 {%0,%1,%2,%3}, [%4];"
                 : "=r"(r0), "=r"(r1), "=r"(r2), "=r"(r3) : "r"(a));
}

#define CPASYNC16(dst, src) asm volatile("cp.async.cg.shared.global [%0], [%1], 16;\n" :: "r"(dst), "l"(src))
#define CPCOMMIT()          asm volatile("cp.async.commit_group;\n")
#define CPWAIT1()           asm volatile("cp.async.wait_group 1;\n")

__device__ __forceinline__ uint32_t smem_u32(const void* p) {
    return (uint32_t)__cvta_generic_to_shared(p);
}

__device__ __forceinline__ void half_body(const float* __restrict__ in,
                                          __half* __restrict__ o, int i)
{
    float4 v = reinterpret_cast<const float4*>(in)[i];
    __half2* op = reinterpret_cast<__half2*>(o) + 2 * i;
    op[0] = __floats2half2_rn(v.x, v.y);
    op[1] = __floats2half2_rn(v.z, v.w);
}

// ---------------- prep: residual copy + x fp16 + all weight fp16, ONE launch -------
__global__ void prep_all_kernel(const float* __restrict__ x,
                                float* __restrict__ resid,
                                __half* __restrict__ xf,
                                const float* __restrict__ w1a, const float* __restrict__ w1b,
                                const float* __restrict__ wxa, const float* __restrict__ wxb,
                                const float* __restrict__ woa, const float* __restrict__ wob,
                                __half* __restrict__ w1f,
                                __half* __restrict__ wxf,
                                __half* __restrict__ wof)
{
    const int NX = MROWS * DIM / 4;
    const int N1 = E2 * DM / 4;
    const int N2 = 64 * DI / 4;
    const int N3 = DM * DI / 4;
    const int NW = N1 + N2 + N3;
    int i = blockIdx.x * 256 + threadIdx.x;
    if (i < NX) {
        float4 v = reinterpret_cast<const float4*>(x)[i];
        reinterpret_cast<float4*>(resid)[i] = v;
        __half2* op = reinterpret_cast<__half2*>(xf) + 2 * i;
        op[0] = __floats2half2_rn(v.x, v.y);
        op[1] = __floats2half2_rn(v.z, v.w);
        return;
    }
    i -= NX;
    if (i >= 2 * NW) return;
    int dir = i / NW;
    i -= dir * NW;
    const float* w1 = dir ? w1b : w1a;
    const float* wx = dir ? wxb : wxa;
    const float* wo = dir ? wob : woa;
    if (i < N1) { half_body(w1, w1f + (long)dir * E2 * DM, i); return; }
    i -= N1;
    if (i < N2) { half_body(wx, wxf + (long)dir * 64 * DI, i); return; }
    i -= N2;
    half_body(wo, wof + (long)dir * DM * DI, i);
}

// ---------------- tensor-core NT GEMM, single fp16, ldmatrix + 3-stage cp.async ----
// Batched over blockIdx.z = dir*nks + kz. OUTH=1 emits __half, else fp32.
template<int BM, int BN, int WM, int WN, int OUTH>
__global__ void __launch_bounds__((BM / WM) * (BN / WN) * 32)
mma_gemm_kernel(const __half* __restrict__ A, const __half* __restrict__ B,
                void* __restrict__ Cv, int ksplit, int nks,
                int lda, long a_dstride, int acol0_step, int flip_is_dir,
                int ldb, long b_dstride,
                int ldc, long c_dstride, int ccol0_step, long csplit_stride)
{
    constexpr int THREADS = (BM / WM) * (BN / WN) * 32;
    constexpr int WM16 = WM / 16;
    constexpr int WN8  = WN / 8;

    __shared__ __align__(16) uint8_t As[3 * BM * 32];   // [stage][BM][32B]
    __shared__ __align__(16) uint8_t Bs[3 * BN * 32];

    const int tid  = threadIdx.x;
    const int bm0  = blockIdx.y * BM;
    const int bn0  = blockIdx.x * BN;
    const int z    = blockIdx.z;
    const int dir  = z / nks;
    const int kz   = z - dir * nks;
    const int kbeg = kz * ksplit;
    const int KT   = ksplit / 16;

    const __half* Ap = A + (long)dir * a_dstride;
    const __half* Bp = B + (long)dir * b_dstride;
    const int acol0 = dir * acol0_step;
    const int ccol0 = dir * ccol0_step;
    const int flip  = flip_is_dir ? dir : 0;
    char* Cb = (char*)Cv + ((long)dir * c_dstride + (long)kz * csplit_stride) * (OUTH ? 2 : 4);

    const int wid  = tid >> 5;
    const int lane = tid & 31;
    const int wm   = wid / (BN / WN);
    const int wn   = wid % (BN / WN);
    const int g    = lane >> 2;
    const int t    = lane & 3;

    float acc[WM16][WN8][4];
#pragma unroll
    for (int i = 0; i < WM16; i++)
#pragma unroll
        for (int j = 0; j < WN8; j++)
#pragma unroll
            for (int q = 0; q < 4; q++) acc[i][j][q] = 0.f;

    auto loadA = [&](int st, int k0) {
        for (int i = tid; i < BM * 2; i += THREADS) {
            int r = i >> 1;
            int c = i & 1;
            int mg = bm0 + r;
            int rowg = mg;
            if (flip) { int b = mg >> 11; int l = mg & 2047; rowg = (b << 11) + (2047 - l); }
            const __half* src = Ap + (long)rowg * lda + acol0 + k0 + c * 8;
            uint32_t dst = smem_u32(As + (st * BM + r) * 32 + ((c ^ ((r >> 2) & 1)) << 4));
            CPASYNC16(dst, src);
        }
    };
    auto loadB = [&](int st, int k0) {
        for (int i = tid; i < BN * 2; i += THREADS) {
            int r = i >> 1;
            int c = i & 1;
            const __half* src = Bp + (long)(bn0 + r) * ldb + k0 + c * 8;
            uint32_t dst = smem_u32(Bs + (st * BN + r) * 32 + ((c ^ ((r >> 2) & 1)) << 4));
            CPASYNC16(dst, src);
        }
    };

    const int a_tile   = lane >> 3;
    const int a_rowoff = ((a_tile & 1) << 3) + (lane & 7);
    const int a_chunk  = a_tile >> 1;
    const int b_rowoff = (((lane >> 4) & 1) << 3) + (lane & 7);
    const int b_chunk  = (lane >> 3) & 1;

    // prologue: stages 0 and 1
    loadA(0, kbeg); loadB(0, kbeg); CPCOMMIT();
    if (KT > 1) { loadA(1, kbeg + 16); loadB(1, kbeg + 16); }
    CPCOMMIT();

    for (int kt = 0; kt < KT; kt++) {
        CPWAIT1();
        __syncthreads();

        if (kt + 2 < KT) { loadA((kt + 2) % 3, kbeg + (kt + 2) * 16); loadB((kt + 2) % 3, kbeg + (kt + 2) * 16); }
        CPCOMMIT();

        const int st = kt % 3;
        const uint8_t* Ah = As + st * BM * 32;
        const uint8_t* Bh = Bs + st * BN * 32;

        uint32_t ah[WM16][4], bh[WN8][2];
#pragma unroll
        for (int i = 0; i < WM16; i++) {
            int r = wm * WM + i * 16 + a_rowoff;
            uint32_t off = r * 32 + (((a_chunk ^ ((r >> 2) & 1))) << 4);
            ldsm_x4(ah[i][0], ah[i][1], ah[i][2], ah[i][3], smem_u32(Ah + off));
        }
#pragma unroll
        for (int jp = 0; jp < WN8 / 2; jp++) {
            int r = wn * WN + jp * 16 + b_rowoff;
            uint32_t off = r * 32 + (((b_chunk ^ ((r >> 2) & 1))) << 4);
            ldsm_x4(bh[2 * jp][0], bh[2 * jp][1], bh[2 * jp + 1][0], bh[2 * jp + 1][1], smem_u32(Bh + off));
        }
#pragma unroll
        for (int i = 0; i < WM16; i++)
#pragma unroll
            for (int j = 0; j < WN8; j++)
                mma_f16(acc[i][j], ah[i], bh[j]);
    }

    // epilogue
#pragma unroll
    for (int i = 0; i < WM16; i++) {
#pragma unroll
        for (int j = 0; j < WN8; j++) {
            int r  = bm0 + wm * WM + i * 16 + g;
            int n0 = bn0 + ccol0 + wn * WN + j * 8 + 2 * t;
            if (OUTH) {
                __half2 h0 = __floats2half2_rn(acc[i][j][0], acc[i][j][1]);
                __half2 h1 = __floats2half2_rn(acc[i][j][2], acc[i][j][3]);
                *reinterpret_cast<__half2*>(Cb + ((long)r * ldc + n0) * 2)       = h0;
                *reinterpret_cast<__half2*>(Cb + ((long)(r + 8) * ldc + n0) * 2) = h1;
            } else {
                float2 v0 = make_float2(acc[i][j][0], acc[i][j][1]);
                float2 v1 = make_float2(acc[i][j][2], acc[i][j][3]);
                *reinterpret_cast<float2*>(Cb + ((long)r * ldc + n0) * 4)       = v0;
                *reinterpret_cast<float2*>(Cb + ((long)(r + 8) * ldc + n0) * 4) = v1;
            }
        }
    }
}

// ---------------- split-K reduction: dbc[dir] = sum_z part[dir][z], both dirs ------
__global__ void reduce_partials_kernel(const float* __restrict__ part, float* __restrict__ dbc)
{
    const int n4 = M64 / 4;                    // per-dir float4 count
    int i = blockIdx.x * 256 + threadIdx.x;    // over 2*n4
    if (i >= 2 * n4) return;
    int dir = i / n4;
    int j = i - dir * n4;
    const float* p = part + (long)dir * KSPLIT * M64;
    float4 a = reinterpret_cast<const float4*>(p)[j];
#pragma unroll
    for (int z = 1; z < KSPLIT; z++) {
        float4 b = reinterpret_cast<const float4*>(p + (long)z * M64)[j];
        a.x += b.x; a.y += b.y; a.z += b.z; a.w += b.w;
    }
    reinterpret_cast<float4*>(dbc + (long)dir * M64)[j] = a;
}

// ---------------- depthwise causal conv(4) + silu, fp16 in, fp16 out ---------------
__global__ void conv_silu_kernel(const __half* __restrict__ xzf_base,
                                 const float* __restrict__ cwa, const float* __restrict__ cwb,
                                 const float* __restrict__ cba, const float* __restrict__ cbb,
                                 __half* __restrict__ xcf_base)
{
    int c  = blockIdx.x * blockDim.x + threadIdx.x;   // channel in [0,DI)
    int l0 = blockIdx.y * 8;
    int zb = blockIdx.z;
    int dir = zb >> 1;
    int b   = zb & 1;

    const float* cw = dir ? cwb : cwa;
    const float* cb = dir ? cbb : cba;
    const __half* xz = xzf_base + (long)dir * MROWS * E2;
    __half* xcf = xcf_base + (long)dir * MROWS * DI;

    float w0 = cw[c * 4 + 0], w1 = cw[c * 4 + 1], w2 = cw[c * 4 + 2], w3 = cw[c * 4 + 3];
    float bias = cb[c];

    float v[11];
#pragma unroll
    for (int j = 0; j < 11; j++) {
        int l = l0 - 3 + j;
        v[j] = (l >= 0) ? __half2float(xz[(long)(b * LL + l) * E2 + c]) : 0.f;
    }
#pragma unroll
    for (int i = 0; i < 8; i++) {
        float a = v[i] * w0 + v[i + 1] * w1 + v[i + 2] * w2 + v[i + 3] * w3 + bias;
        float s = a / (1.f + __expf(-a));   // silu
        xcf[(long)(b * LL + l0 + i) * DI + c] = __float2half(s);
    }
}

// ---------------- delta = softplus(dt @ dt_w^T + dt_b), fp16 out -------------------
__global__ void delta_kernel(const float* __restrict__ dbc_base,
                             const float* __restrict__ dwa, const float* __restrict__ dwb,
                             const float* __restrict__ dba, const float* __restrict__ dbb,
                             __half* __restrict__ delta_base)
{
    int d   = blockIdx.x * 256 + threadIdx.x;  // [0,DI)
    int m0  = blockIdx.y * 4;
    int dir = blockIdx.z;

    const float* dt_w = dir ? dwb : dwa;
    const float* dt_b = dir ? dbb : dba;
    const float* dbc = dbc_base + (long)dir * M64;
    __half* delta = delta_base + (long)dir * MROWS * DI;

    float w[DTR];
    const float4* w4 = reinterpret_cast<const float4*>(dt_w + (long)d * DTR);
#pragma unroll
    for (int r = 0; r < DTR / 4; r++) {
        float4 v = w4[r];
        w[4 * r + 0] = v.x; w[4 * r + 1] = v.y; w[4 * r + 2] = v.z; w[4 * r + 3] = v.w;
    }
    float bias = dt_b[d];

#pragma unroll
    for (int mi = 0; mi < 4; mi++) {
        const float* row = dbc + (long)(m0 + mi) * 64;
        float acc = bias;
#pragma unroll
        for (int r = 0; r < DTR; r++) acc = fmaf(row[r], w[r], acc);
        float sp = (acc > 20.f) ? acc : log1pf(__expf(acc));
        delta[(long)(m0 + mi) * DI + d] = __float2half(sp);
    }
}

// ---------------- scan pass1: chunk-local scan from h=0, batched -------------------
__global__ void scan_pass1_kernel(const __half* __restrict__ delta_base,
                                  const __half* __restrict__ xcf_base,
                                  const float* __restrict__ dbc_base,
                                  const float* __restrict__ Aa_, const float* __restrict__ Ab_,
                                  float* __restrict__ cs_base,
                                  float* __restrict__ he_base)
{
    __shared__ float sB[LC][DS];
    int chunk = blockIdx.x;
    int d     = blockIdx.y * 256 + threadIdx.x;
    int zb    = blockIdx.z;
    int dir   = zb >> 1;
    int b     = zb & 1;
    int m0    = b * LL + chunk * LC;

    const float* A_log = dir ? Ab_ : Aa_;
    const __half* delta = delta_base + (long)dir * MROWS * DI;
    const __half* xcf   = xcf_base   + (long)dir * MROWS * DI;
    const float* dbc    = dbc_base   + (long)dir * M64;
    float* cs = cs_base + (long)dir * BB * NC * DI;
    float* he = he_base + (long)dir * BB * NC * DI * DS;

    const float* dbc0 = dbc + (long)m0 * 64;
    for (int i = threadIdx.x; i < LC * DS; i += 256) {
        int tt = i >> 4, s = i & 15;
        sB[tt][s] = dbc0[tt * 64 + 32 + s];
    }
    __syncthreads();

    float Aa[DS];
#pragma unroll
    for (int s = 0; s < DS; s++) Aa[s] = -__expf(A_log[d * DS + s]);
    float a0 = Aa[0];
    bool fast = true;
#pragma unroll
    for (int s = 1; s < DS; s++) fast = fast && (fabsf(Aa[s] - (s + 1) * a0) < 1e-4f * fabsf(Aa[s]));

    float h[DS];
#pragma unroll
    for (int s = 0; s < DS; s++) h[s] = 0.f;
    float S = 0.f;

    if (fast) {
        for (int tt = 0; tt < LC; tt++) {
            int m = m0 + tt;
            float dlt = __half2float(delta[(long)m * DI + d]);
            float xcv = __half2float(xcf[(long)m * DI + d]);
            S += dlt;
            float du = dlt * xcv;
            float e1 = __expf(dlt * a0);
            float p = e1;
#pragma unroll
            for (int s = 0; s < DS; s++) {
                h[s] = fmaf(h[s], p, du * sB[tt][s]);
                p *= e1;
            }
        }
    } else {
        for (int tt = 0; tt < LC; tt++) {
            int m = m0 + tt;
            float dlt = __half2float(delta[(long)m * DI + d]);
            float xcv = __half2float(xcf[(long)m * DI + d]);
            S += dlt;
            float du = dlt * xcv;
#pragma unroll
            for (int s = 0; s < DS; s++) {
                float da = __expf(dlt * Aa[s]);
                h[s] = fmaf(h[s], da, du * sB[tt][s]);
            }
        }
    }

    cs[(long)(b * NC + chunk) * DI + d] = S;
    float* hout = he + ((long)(b * NC + chunk) * DI + d) * DS;
#pragma unroll
    for (int s = 0; s < DS; s++) hout[s] = h[s];
}

// ---------------- scan fixup: sequential over the 16 chunks, batched ---------------
__global__ void scan_fixup_kernel(const float* __restrict__ cs_base,
                                  const float* __restrict__ he_base,
                                  const float* __restrict__ Aa_, const float* __restrict__ Ab_,
                                  float* __restrict__ hs_base)
{
    int idx = blockIdx.x * 256 + threadIdx.x;      // 2*BB*DI*DS threads
    int s = idx & 15;
    int d = (idx >> 4) & (DI - 1);
    int b = (idx >> 14) & 1;
    int dir = idx >> 15;

    const float* A_log = dir ? Ab_ : Aa_;
    const float* cs = cs_base + (long)dir * BB * NC * DI;
    const float* he = he_base + (long)dir * BB * NC * DI * DS;
    float* hs = hs_base + (long)dir * BB * NC * DI * DS;

    float A = -__expf(A_log[d * DS + s]);
    float h = 0.f;
    for (int c = 0; c < NC; c++) {
        long base = ((long)(b * NC + c) * DI + d) * DS + s;
        hs[base] = h;
        float S = cs[(long)(b * NC + c) * DI + d];
        h = __expf(A * S) * h + he[base];
    }
}

// ---------------- scan pass3: replay with h_start, emit gated y (fp16) -------------
__global__ void scan_pass3_kernel(const __half* __restrict__ delta_base,
                                  const __half* __restrict__ xcf_base,
                                  const float* __restrict__ dbc_base,
                                  const float* __restrict__ Aa_, const float* __restrict__ Ab_,
                                  const float* __restrict__ hs_base,
                                  const float* __restrict__ Da_, const float* __restrict__ Db_,
                                  const __half* __restrict__ xzf_base,
                                  __half* __restrict__ ymf_base)
{
    __shared__ float sB[LC][DS];
    __shared__ float sC[LC][DS];
    int chunk = blockIdx.x;
    int d     = blockIdx.y * 256 + threadIdx.x;
    int zb    = blockIdx.z;
    int dir   = zb >> 1;
    int b     = zb & 1;
    int m0    = b * LL + chunk * LC;

    const float* A_log = dir ? Ab_ : Aa_;
    const float* Dp    = dir ? Db_ : Da_;
    const __half* delta = delta_base + (long)dir * MROWS * DI;
    const __half* xcf   = xcf_base   + (long)dir * MROWS * DI;
    const float* dbc    = dbc_base   + (long)dir * M64;
    const float* hs     = hs_base    + (long)dir * BB * NC * DI * DS;
    const __half* xzf   = xzf_base   + (long)dir * MROWS * E2;
    __half* ymf = ymf_base + (long)dir * MROWS * DI;

    const float* dbc0 = dbc + (long)m0 * 64;
    for (int i = threadIdx.x; i < LC * DS; i += 256) {
        int tt = i >> 4, s = i & 15;
        sB[tt][s] = dbc0[tt * 64 + 32 + s];
        sC[tt][s] = dbc0[tt * 64 + 48 + s];
    }
    __syncthreads();

    float Aa[DS];
#pragma unroll
    for (int s = 0; s < DS; s++) Aa[s] = -__expf(A_log[d * DS + s]);
    float a0 = Aa[0];
    bool fast = true;
#pragma unroll
    for (int s = 1; s < DS; s++) fast = fast && (fabsf(Aa[s] - (s + 1) * a0) < 1e-4f * fabsf(Aa[s]));

    float h[DS];
    const float* hin = hs + ((long)(b * NC + chunk) * DI + d) * DS;
#pragma unroll
    for (int s = 0; s < DS; s++) h[s] = hin[s];

    float Dv = Dp[d];

    for (int tt = 0; tt < LC; tt++) {
        int m = m0 + tt;
        float dlt = __half2float(delta[(long)m * DI + d]);
        float xcv = __half2float(xcf[(long)m * DI + d]);
        float du = dlt * xcv;
        float y = 0.f;
        if (fast) {
            float e1 = __expf(dlt * a0);
            float p = e1;
#pragma unroll
            for (int s = 0; s < DS; s++) {
                h[s] = fmaf(h[s], p, du * sB[tt][s]);
                y = fmaf(h[s], sC[tt][s], y);
                p *= e1;
            }
        } else {
#pragma unroll
            for (int s = 0; s < DS; s++) {
                float da = __expf(dlt * Aa[s]);
                h[s] = fmaf(h[s], da, du * sB[tt][s]);
                y = fmaf(h[s], sC[tt][s], y);
            }
        }
        float z = __half2float(xzf[(long)m * E2 + DI + d]);
        float sil = z / (1.f + __expf(-z));
        float out = (y + xcv * Dv) * sil;
        ymf[(long)m * DI + d] = __float2half(out);
    }
}

// ---------------- host launcher ---------------------------------------------------
extern "C" void kernel_launch(void* const* d_in, const int* in_sizes, int n_in,
                              void* d_out, int out_size)
{
    const float* x = (const float*)d_in[0];
    float* out = (float*)d_out;

    float *part, *dbc, *cs, *he, *hs;
    cudaGetSymbolAddress((void**)&part,  g_part);
    cudaGetSymbolAddress((void**)&dbc,   g_dbc);
    cudaGetSymbolAddress((void**)&cs,    g_cs);
    cudaGetSymbolAddress((void**)&he,    g_he);
    cudaGetSymbolAddress((void**)&hs,    g_hs);

    __half *xf, *w1f, *wxf, *wof, *xzf, *xcf, *dltf, *ymf;
    cudaGetSymbolAddress((void**)&xf,   g_xf);
    cudaGetSymbolAddress((void**)&w1f,  g_w1f);
    cudaGetSymbolAddress((void**)&wxf,  g_wxf);
    cudaGetSymbolAddress((void**)&wof,  g_wof);
    cudaGetSymbolAddress((void**)&xzf,  g_xzf);
    cudaGetSymbolAddress((void**)&xcf,  g_xcf);
    cudaGetSymbolAddress((void**)&dltf, g_dltf);
    cudaGetSymbolAddress((void**)&ymf,  g_ymf);

    // per-direction input pointers
    const float* in_w[2];  const float* conv_w[2]; const float* conv_b[2];
    const float* xproj_w[2]; const float* dt_w[2]; const float* dt_b[2];
    const float* A_log[2]; const float* Dp[2];     const float* out_w[2];
    for (int dir = 0; dir < 2; dir++) {
        in_w[dir]    = (const float*)d_in[1 + dir * 9 + 0];
        conv_w[dir]  = (const float*)d_in[1 + dir * 9 + 1];
        conv_b[dir]  = (const float*)d_in[1 + dir * 9 + 2];
        xproj_w[dir] = (const float*)d_in[1 + dir * 9 + 3];
        dt_w[dir]    = (const float*)d_in[1 + dir * 9 + 4];
        dt_b[dir]    = (const float*)d_in[1 + dir * 9 + 5];
        A_log[dir]   = (const float*)d_in[1 + dir * 9 + 6];
        Dp[dir]      = (const float*)d_in[1 + dir * 9 + 7];
        out_w[dir]   = (const float*)d_in[1 + dir * 9 + 8];
    }

    const long HID = (long)MROWS * DIM;
    const int NTOT = (MROWS * DIM / 4) + 2 * ((E2 * DM / 4) + (64 * DI / 4) + (DM * DI / 4));

    // 1) fused prep: residual copy + x fp16 + all weights fp16
    prep_all_kernel<<<(NTOT + 255) / 256, 256>>>(
        x, out + HID, xf,
        in_w[0], in_w[1], xproj_w[0], xproj_w[1], out_w[0], out_w[1],
        w1f, wxf, wof);

    // 2) xz[dir] = x_dir @ in_w[dir]^T  (M=4096, N=2048, K=512), fp16 out
    mma_gemm_kernel<128, 128, 64, 32, 1><<<dim3(E2 / 128, MROWS / 128, 2), 256>>>(
        xf, w1f, xzf, DM, 1,
        /*lda*/ DIM, /*a_dstride*/ 0, /*acol0_step*/ DM, /*flip_is_dir*/ 1,
        /*ldb*/ DM, /*b_dstride*/ (long)E2 * DM,
        /*ldc*/ E2, /*c_dstride*/ (long)MROWS * E2, /*ccol0_step*/ 0, 0);

    // 3) conv + silu, both dirs (fp16 in, fp16 out only)
    conv_silu_kernel<<<dim3(DI / 256, LL / 8, 2 * BB), 256>>>(
        xzf, conv_w[0], conv_w[1], conv_b[0], conv_b[1], xcf);

    // 4) part[dir][kz] = xc @ xproj_w^T  (split-K=4), then compact reduce -> dbc
    mma_gemm_kernel<64, 64, 32, 32, 0><<<dim3(1, MROWS / 64, 2 * KSPLIT), 128>>>(
        xcf, wxf, part, DI / KSPLIT, KSPLIT,
        DI, (long)MROWS * DI, 0, 0,
        DI, (long)64 * DI,
        64, (long)KSPLIT * M64, 0, (long)M64);
    reduce_partials_kernel<<<(2 * M64 / 4 + 255) / 256, 256>>>(part, dbc);

    // 5) delta (fp16 out), both dirs
    delta_kernel<<<dim3(DI / 256, MROWS / 4, 2), 256>>>(
        dbc, dt_w[0], dt_w[1], dt_b[0], dt_b[1], dltf);

    // 6-8) chunked parallel scan, both dirs (fp16 delta/xc streams)
    scan_pass1_kernel<<<dim3(NC, DI / 256, 2 * BB), 256>>>(
        dltf, xcf, dbc, A_log[0], A_log[1], cs, he);
    scan_fixup_kernel<<<(2 * BB * DI * DS) / 256, 256>>>(
        cs, he, A_log[0], A_log[1], hs);
    scan_pass3_kernel<<<dim3(NC, DI / 256, 2 * BB), 256>>>(
        dltf, xcf, dbc, A_log[0], A_log[1], hs, Dp[0], Dp[1], xzf, ymf);

    // 9) hidden[:, :, dir*512:+512] = ym @ out_w^T  (M=4096, N=512, K=1024), fp32 out
    mma_gemm_kernel<128, 128, 64, 32, 0><<<dim3(DM / 128, MROWS / 128, 2), 256>>>(
        ymf, wof, out, DI, 1,
        DI, (long)MROWS * DI, 0, 0,
        DI, (long)DM * DI,
        DIM, 0, DM, 0);
}